// round 5
// baseline (speedup 1.0000x reference)
#include <cuda_runtime.h>
#include <math.h>

#define BATCH 256
#define SEQ   512
#define ISZ   256
#define HSZ   512
#define G4    2048   // 4*HSZ gate-interleaved: col j = u*4 + g, g in {i,f,g,o}

typedef unsigned long long ull;

// ---------------- device scratch (allocation-free) ----------------
__device__ float g_xu[(size_t)SEQ * BATCH * G4];  // xu[t][b][j]
__device__ float g_h[2][BATCH * HSZ];             // double-buffered hidden state
__device__ unsigned g_arrive;                     // grid-sync counter (reset by xu)

// ---------------- f32x2 helpers ----------------
__device__ __forceinline__ ull fma2(ull a, ull b, ull c) {
    ull d;
    asm("fma.rn.f32x2 %0, %1, %2, %3;" : "=l"(d) : "l"(a), "l"(b), "l"(c));
    return d;
}
__device__ __forceinline__ float2 unpk(ull v) {
    float2 r;
    asm("mov.b64 {%0, %1}, %2;" : "=f"(r.x), "=f"(r.y) : "l"(v));
    return r;
}
__device__ __forceinline__ float fsig(float x)  { return 1.0f / (1.0f + __expf(-x)); }
__device__ __forceinline__ float ftanh(float x) { return 2.0f / (1.0f + __expf(-2.0f * x)) - 1.0f; }

__device__ __forceinline__ void arrive_release(unsigned* p) {
    asm volatile("red.release.gpu.global.add.u32 [%0], 1;" :: "l"(p) : "memory");
}
__device__ __forceinline__ unsigned poll_acquire(const unsigned* p) {
    unsigned v;
    asm volatile("ld.acquire.gpu.global.u32 %0, [%1];" : "=r"(v) : "l"(p) : "memory");
    return v;
}

// ============ phase 1: xu = x @ Wu (interleaved on the fly) + bias ==========
// GEMM M = SEQ*BATCH (m -> t=m>>8, b=m&255), N = 2048, K = 256.
// f32x2 column-pair scheme: A pre-duplicated in smem, no dup movs.
#define XBM 64
#define XBN 64
#define XBK 16
#define XAS 34   // word stride of duplicated-A rows (16 float2 + 1 pad)

__global__ __launch_bounds__(256) void xu_kernel(
    const float* __restrict__ x,
    const float* __restrict__ Wui, const float* __restrict__ Wuf,
    const float* __restrict__ Wug, const float* __restrict__ Wuo,
    const float* __restrict__ bi,  const float* __restrict__ bf,
    const float* __restrict__ bg,  const float* __restrict__ bo) {
    __shared__ float As[XBM * XAS];   // [row][2k {dup}]
    __shared__ float Bs[XBK * XBN];   // [k][col interleaved]

    if (blockIdx.x == 0 && blockIdx.y == 0 && threadIdx.x == 0) g_arrive = 0u;

    int m0 = blockIdx.y * XBM;
    int n0 = blockIdx.x * XBN;
    int tid = threadIdx.x;
    int tx = tid & 15;
    int ty = tid >> 4;

    int prow = tid >> 2;        // 0..63
    int pkof = (tid & 3) * 4;   // 0,4,8,12
    int brow = tid >> 4;        // 0..15
    int bu   = tid & 15;        // 0..15

    int m = m0 + prow;
    int t = m >> 8;
    int b = m & 255;
    const float* aptr = x + (size_t)b * (SEQ * ISZ) + (size_t)t * ISZ + pkof;
    int ubase = (n0 >> 2) + bu;

    ull acc[4][2] = {};

    for (int k0 = 0; k0 < ISZ; k0 += XBK) {
        float4 av = *(const float4*)(aptr + k0);
        *(float2*)&As[prow * XAS + 2 * (pkof + 0)] = make_float2(av.x, av.x);
        *(float2*)&As[prow * XAS + 2 * (pkof + 1)] = make_float2(av.y, av.y);
        *(float2*)&As[prow * XAS + 2 * (pkof + 2)] = make_float2(av.z, av.z);
        *(float2*)&As[prow * XAS + 2 * (pkof + 3)] = make_float2(av.w, av.w);
        int kr = (k0 + brow) * HSZ + ubase;
        Bs[brow * XBN + bu * 4 + 0] = Wui[kr];
        Bs[brow * XBN + bu * 4 + 1] = Wuf[kr];
        Bs[brow * XBN + bu * 4 + 2] = Wug[kr];
        Bs[brow * XBN + bu * 4 + 3] = Wuo[kr];
        __syncthreads();

#pragma unroll
        for (int kk = 0; kk < XBK; kk++) {
            ulonglong2 b2 = *(const ulonglong2*)&Bs[kk * XBN + tx * 4];
#pragma unroll
            for (int r = 0; r < 4; r++) {
                ull a2 = *(const ull*)&As[(ty * 4 + r) * XAS + 2 * kk];
                acc[r][0] = fma2(a2, b2.x, acc[r][0]);
                acc[r][1] = fma2(a2, b2.y, acc[r][1]);
            }
        }
        __syncthreads();
    }

    int u = (n0 >> 2) + tx;
    float4 bias = {bi[u], bf[u], bg[u], bo[u]};
#pragma unroll
    for (int r = 0; r < 4; r++) {
        float2 lo = unpk(acc[r][0]);
        float2 hi = unpk(acc[r][1]);
        float4 ov = {lo.x + bias.x, lo.y + bias.y, hi.x + bias.z, hi.y + bias.w};
        *(float4*)(g_xu + (size_t)(m0 + ty * 4 + r) * G4 + n0 + tx * 4) = ov;
    }
}

// ============ phase 2: PERSISTENT, all 512 steps =============================
// 128 blocks x 512 threads (two 256-thread K-halves per block), 1 CTA/SM.
// W_h slice (512x64) staged in smem once; A pre-duplicated; partial accs
// combined through smem; cell state in registers; grid sync between steps.
#define PBLKS 128
#define PN 64
#define PM 64
#define EPS 68                              // word stride for A / partial rows
#define WHS_FLOATS (HSZ * PN)               // 32768
#define AS_FLOATS  (PM * EPS)               // 4352
#define P_SMEM_BYTES ((WHS_FLOATS + 2 * AS_FLOATS) * 4)   // 165888 B

extern __shared__ float s_mem[];

__global__ __launch_bounds__(512, 1) void lstm_persistent(
    float* __restrict__ out,
    const float* __restrict__ Whi, const float* __restrict__ Whf,
    const float* __restrict__ Whg, const float* __restrict__ Who) {
    float* Whs = s_mem;                     // [512][64]
    float* As0 = s_mem + WHS_FLOATS;        // half 0: dup-A / partials
    float* As1 = As0 + AS_FLOATS;           // half 1

    int tid = threadIdx.x;
    int bx = blockIdx.x & 31;               // 32 n-tiles
    int by = blockIdx.x >> 5;               // 4 batch-tiles
    int n0 = bx * PN;
    int b0 = by * PM;

    int tx = tid & 15;                      // col quad
    int ty = (tid >> 4) & 15;               // row quad
    int half = tid >> 8;                    // K-half
    int htid = tid & 255;
    int prow = htid >> 2;                   // 0..63 staging row
    int pkof = (htid & 3) * 8;              // k offset within 32-chunk

    int er = tid >> 3;                      // epilogue row 0..63
    int ec = (tid & 7) * 8;                 // epilogue col base (2 units)
    int uA = (n0 >> 2) + (tid & 7) * 2;     // first unit of this thread

    float* As_h = half ? As1 : As0;

    // ---- stage W_h slice (gate-interleaved on the fly), once ----
    for (int idx = tid; idx < WHS_FLOATS; idx += 512) {
        int k = idx >> 6, c = idx & 63;
        int u = (n0 >> 2) + (c >> 2), g = c & 3;
        const float* W = (g == 0) ? Whi : (g == 1) ? Whf : (g == 2) ? Whg : Who;
        Whs[idx] = W[k * HSZ + u];
    }
    __syncthreads();

    float cA = 0.0f, cB = 0.0f;             // register cell state (2 units x 1 row)

    for (int t = 0; t < SEQ; t++) {
        const float* __restrict__ h_in = g_h[t & 1];
        float* __restrict__ h_out = (t == SEQ - 1) ? out : g_h[(t + 1) & 1];

        // prefetch this thread's xu gates early (consumed in epilogue)
        const float* xp = g_xu + ((size_t)t * BATCH + b0 + er) * G4 + n0 + ec;
        float4 xva = __ldcg((const float4*)xp);
        float4 xvb = __ldcg((const float4*)(xp + 4));

        ull acc[4][2] = {};

        if (t > 0) {
            const float* aptr = h_in + (size_t)(b0 + prow) * HSZ + half * 256 + pkof;
            float4 pa = __ldcg((const float4*)aptr);
            float4 pb = __ldcg((const float4*)(aptr + 4));

            for (int s = 0; s < 8; s++) {
                *(float2*)&As_h[prow * EPS + 2 * (pkof + 0)] = make_float2(pa.x, pa.x);
                *(float2*)&As_h[prow * EPS + 2 * (pkof + 1)] = make_float2(pa.y, pa.y);
                *(float2*)&As_h[prow * EPS + 2 * (pkof + 2)] = make_float2(pa.z, pa.z);
                *(float2*)&As_h[prow * EPS + 2 * (pkof + 3)] = make_float2(pa.w, pa.w);
                *(float2*)&As_h[prow * EPS + 2 * (pkof + 4)] = make_float2(pb.x, pb.x);
                *(float2*)&As_h[prow * EPS + 2 * (pkof + 5)] = make_float2(pb.y, pb.y);
                *(float2*)&As_h[prow * EPS + 2 * (pkof + 6)] = make_float2(pb.z, pb.z);
                *(float2*)&As_h[prow * EPS + 2 * (pkof + 7)] = make_float2(pb.w, pb.w);
                __syncthreads();

                if (s < 7) {
                    pa = __ldcg((const float4*)(aptr + (s + 1) * 32));
                    pb = __ldcg((const float4*)(aptr + (s + 1) * 32 + 4));
                }

                const float* WB = Whs + (size_t)(half * 256 + s * 32) * PN + tx * 4;
#pragma unroll
                for (int kk = 0; kk < 32; kk++) {
                    ulonglong2 b2 = *(const ulonglong2*)(WB + kk * PN);
#pragma unroll
                    for (int r = 0; r < 4; r++) {
                        ull a2 = *(const ull*)&As_h[(ty * 4 + r) * EPS + 2 * kk];
                        acc[r][0] = fma2(a2, b2.x, acc[r][0]);
                        acc[r][1] = fma2(a2, b2.y, acc[r][1]);
                    }
                }
                __syncthreads();
            }
        }

        // ---- write partial accs (reuse As buffers as EP0/EP1) ----
        float* EPh = half ? As1 : As0;
#pragma unroll
        for (int r = 0; r < 4; r++) {
            float2 lo = unpk(acc[r][0]);
            float2 hi = unpk(acc[r][1]);
            float4 v = {lo.x, lo.y, hi.x, hi.y};
            *(float4*)&EPh[(ty * 4 + r) * EPS + tx * 4] = v;
        }
        __syncthreads();

        // ---- combine halves + fused LSTM cell (each thread: 1 row, 2 units) --
        float4 pA = *(const float4*)&As0[er * EPS + ec];
        float4 pB = *(const float4*)&As0[er * EPS + ec + 4];
        float4 qA = *(const float4*)&As1[er * EPS + ec];
        float4 qB = *(const float4*)&As1[er * EPS + ec + 4];

        float iA = fsig (pA.x + qA.x + xva.x);
        float fA = fsig (pA.y + qA.y + xva.y);
        float gA = ftanh(pA.z + qA.z + xva.z);
        float oA = fsig (pA.w + qA.w + xva.w);
        float iB = fsig (pB.x + qB.x + xvb.x);
        float fB = fsig (pB.y + qB.y + xvb.y);
        float gB = ftanh(pB.z + qB.z + xvb.z);
        float oB = fsig (pB.w + qB.w + xvb.w);

        cA = fA * cA + iA * gA;
        cB = fB * cB + iB * gB;
        float2 hv = {oA * ftanh(cA), oB * ftanh(cB)};
        *(float2*)&h_out[(size_t)(b0 + er) * HSZ + uA] = hv;

        // ---- grid-wide sync (signed wrap-distance compare: cannot hang even
        //      if the counter starts non-zero, e.g. profiler kernel replay) ----
        if (t < SEQ - 1) {
            __syncthreads();
            if (tid == 0) {
                arrive_release(&g_arrive);
                unsigned target = (unsigned)(t + 1) * (unsigned)PBLKS;
                while ((int)(poll_acquire(&g_arrive) - target) < 0) {
                    __nanosleep(32);
                }
            }
            __syncthreads();
        }
    }
}

// ---------------- launch ----------------------------------------------------
extern "C" void kernel_launch(void* const* d_in, const int* in_sizes, int n_in,
                              void* d_out, int out_size) {
    const float* x   = (const float*)d_in[0];
    const float* Wui = (const float*)d_in[1];
    const float* Whi = (const float*)d_in[2];
    const float* bi  = (const float*)d_in[3];
    const float* Wuf = (const float*)d_in[4];
    const float* Whf = (const float*)d_in[5];
    const float* bf  = (const float*)d_in[6];
    const float* Wug = (const float*)d_in[7];
    const float* Whg = (const float*)d_in[8];
    const float* bg  = (const float*)d_in[9];
    const float* Wuo = (const float*)d_in[10];
    const float* Who = (const float*)d_in[11];
    const float* bo  = (const float*)d_in[12];
    float* out = (float*)d_out;

    cudaFuncSetAttribute(lstm_persistent,
                         cudaFuncAttributeMaxDynamicSharedMemorySize, P_SMEM_BYTES);

    dim3 xu_grid(G4 / XBN, (SEQ * BATCH) / XBM);   // (32, 2048)
    xu_kernel<<<xu_grid, 256>>>(x, Wui, Wuf, Wug, Wuo, bi, bf, bg, bo);

    lstm_persistent<<<PBLKS, 512, P_SMEM_BYTES>>>(out, Whi, Whf, Whg, Who);
}

// round 6
// speedup vs baseline: 1.2183x; 1.2183x over previous
#include <cuda_runtime.h>
#include <math.h>

#define BATCH 256
#define SEQ   512
#define ISZ   256
#define HSZ   512
#define G4    2048   // 4*HSZ gate-interleaved: col j = u*4 + g, g in {i,f,g,o}

typedef unsigned long long ull;

// ---------------- device scratch (allocation-free) ----------------
__device__ float g_xu[(size_t)SEQ * BATCH * G4];  // xu[t][b][j]
__device__ float g_h[2][BATCH * HSZ];             // double-buffered hidden state
__device__ unsigned g_arrive;                     // grid-sync counter (reset by xu)

// ---------------- f32x2 helpers ----------------
__device__ __forceinline__ ull fma2(ull a, ull b, ull c) {
    ull d;
    asm("fma.rn.f32x2 %0, %1, %2, %3;" : "=l"(d) : "l"(a), "l"(b), "l"(c));
    return d;
}
__device__ __forceinline__ ull dup2(float x) {
    ull d;
    asm("mov.b64 %0, {%1, %1};" : "=l"(d) : "f"(x));
    return d;
}
__device__ __forceinline__ float2 unpk(ull v) {
    float2 r;
    asm("mov.b64 {%0, %1}, %2;" : "=f"(r.x), "=f"(r.y) : "l"(v));
    return r;
}
__device__ __forceinline__ float fsig(float x)  { return 1.0f / (1.0f + __expf(-x)); }
__device__ __forceinline__ float ftanh(float x) { return 2.0f / (1.0f + __expf(-2.0f * x)) - 1.0f; }

__device__ __forceinline__ void arrive_release(unsigned* p) {
    asm volatile("red.release.gpu.global.add.u32 [%0], 1;" :: "l"(p) : "memory");
}
__device__ __forceinline__ unsigned poll_acquire(const unsigned* p) {
    unsigned v;
    asm volatile("ld.acquire.gpu.global.u32 %0, [%1];" : "=r"(v) : "l"(p) : "memory");
    return v;
}

// ============ phase 1: xu = x @ Wu (interleaved on the fly) + bias ==========
#define XBM 64
#define XBN 64
#define XBK 16
#define XAS 34   // word stride of duplicated-A rows (16 float2 + 1 pad)

__global__ __launch_bounds__(256) void xu_kernel(
    const float* __restrict__ x,
    const float* __restrict__ Wui, const float* __restrict__ Wuf,
    const float* __restrict__ Wug, const float* __restrict__ Wuo,
    const float* __restrict__ bi,  const float* __restrict__ bf,
    const float* __restrict__ bg,  const float* __restrict__ bo) {
    __shared__ float As[XBM * XAS];
    __shared__ float Bs[XBK * XBN];

    if (blockIdx.x == 0 && blockIdx.y == 0 && threadIdx.x == 0) g_arrive = 0u;

    int m0 = blockIdx.y * XBM;
    int n0 = blockIdx.x * XBN;
    int tid = threadIdx.x;
    int tx = tid & 15;
    int ty = tid >> 4;

    int prow = tid >> 2;
    int pkof = (tid & 3) * 4;
    int brow = tid >> 4;
    int bu   = tid & 15;

    int m = m0 + prow;
    int t = m >> 8;
    int b = m & 255;
    const float* aptr = x + (size_t)b * (SEQ * ISZ) + (size_t)t * ISZ + pkof;
    int ubase = (n0 >> 2) + bu;

    ull acc[4][2] = {};

    for (int k0 = 0; k0 < ISZ; k0 += XBK) {
        float4 av = *(const float4*)(aptr + k0);
        *(float2*)&As[prow * XAS + 2 * (pkof + 0)] = make_float2(av.x, av.x);
        *(float2*)&As[prow * XAS + 2 * (pkof + 1)] = make_float2(av.y, av.y);
        *(float2*)&As[prow * XAS + 2 * (pkof + 2)] = make_float2(av.z, av.z);
        *(float2*)&As[prow * XAS + 2 * (pkof + 3)] = make_float2(av.w, av.w);
        int kr = (k0 + brow) * HSZ + ubase;
        Bs[brow * XBN + bu * 4 + 0] = Wui[kr];
        Bs[brow * XBN + bu * 4 + 1] = Wuf[kr];
        Bs[brow * XBN + bu * 4 + 2] = Wug[kr];
        Bs[brow * XBN + bu * 4 + 3] = Wuo[kr];
        __syncthreads();

#pragma unroll
        for (int kk = 0; kk < XBK; kk++) {
            ulonglong2 b2 = *(const ulonglong2*)&Bs[kk * XBN + tx * 4];
#pragma unroll
            for (int r = 0; r < 4; r++) {
                ull a2 = *(const ull*)&As[(ty * 4 + r) * XAS + 2 * kk];
                acc[r][0] = fma2(a2, b2.x, acc[r][0]);
                acc[r][1] = fma2(a2, b2.y, acc[r][1]);
            }
        }
        __syncthreads();
    }

    int u = (n0 >> 2) + tx;
    float4 bias = {bi[u], bf[u], bg[u], bo[u]};
#pragma unroll
    for (int r = 0; r < 4; r++) {
        float2 lo = unpk(acc[r][0]);
        float2 hi = unpk(acc[r][1]);
        float4 ov = {lo.x + bias.x, lo.y + bias.y, hi.x + bias.z, hi.y + bias.w};
        *(float4*)(g_xu + (size_t)(m0 + ty * 4 + r) * G4 + n0 + tx * 4) = ov;
    }
}

// ============ phase 2: PERSISTENT, all 512 steps =============================
// 128 blocks x 512 threads (two 256-thread K-halves). Row-pair f32x2 inner
// loop (raw A, dup-movs for B on alu pipe). A transposed via XOR-swizzled
// conflict-free STS, ping-pong buffered (1 sync per 32-k chunk).
#define PBLKS 128
#define PN 64
#define PM 64
#define AST 64                              // A buffer row stride (swizzle, no pad)
#define CHUNK 32
#define EPS 68                              // partials row stride
#define WHS_FLOATS (HSZ * PN)               // 32768
#define ABUF_FLOATS (CHUNK * AST)           // 2048 (per buffer)
#define EP_FLOATS  (PM * EPS)               // 4352 (per half)
// smem: Whs + 2 halves * 2 ping-pong A bufs + 2 EP = 49664 floats = 198656 B
#define P_SMEM_BYTES ((WHS_FLOATS + 4 * ABUF_FLOATS + 2 * EP_FLOATS) * 4)

extern __shared__ float s_mem[];

__global__ __launch_bounds__(512, 1) void lstm_persistent(
    float* __restrict__ out,
    const float* __restrict__ Whi, const float* __restrict__ Whf,
    const float* __restrict__ Whg, const float* __restrict__ Who) {
    float* Whs = s_mem;                               // [512][64]
    float* Abuf = s_mem + WHS_FLOATS;                 // [half][pp][32][64]
    float* EP0 = s_mem + WHS_FLOATS + 4 * ABUF_FLOATS;
    float* EP1 = EP0 + EP_FLOATS;

    int tid = threadIdx.x;
    int bx = blockIdx.x & 31;
    int by = blockIdx.x >> 5;
    int n0 = bx * PN;
    int b0 = by * PM;

    int tx = tid & 15;                      // col quad (one unit)
    int ty = (tid >> 4) & 15;               // row quad
    int half = tid >> 8;
    int htid = tid & 255;
    int prow = htid >> 2;                   // 0..63 staging row
    int pkof = (htid & 3) * 8;              // 0,8,16,24

    int er = tid >> 3;                      // epilogue row 0..63
    int ec = (tid & 7) * 8;                 // epilogue col base
    int uA = (n0 >> 2) + (tid & 7) * 2;

    float* myA = Abuf + half * 2 * ABUF_FLOATS;   // this half's two buffers
    int scol = prow ^ pkof;                       // swizzled store column
    int ty4 = ty * 4;

    // ---- stage W_h slice (gate-interleaved on the fly), once ----
    for (int idx = tid; idx < WHS_FLOATS; idx += 512) {
        int k = idx >> 6, c = idx & 63;
        int u = (n0 >> 2) + (c >> 2), g = c & 3;
        const float* W = (g == 0) ? Whi : (g == 1) ? Whf : (g == 2) ? Whg : Who;
        Whs[idx] = W[k * HSZ + u];
    }
    __syncthreads();

    float cA = 0.0f, cB = 0.0f;

    for (int t = 0; t < SEQ; t++) {
        const float* __restrict__ h_in = g_h[t & 1];
        float* __restrict__ h_out = (t == SEQ - 1) ? out : g_h[(t + 1) & 1];

        // prefetch this thread's xu gates (consumed in epilogue)
        const float* xp = g_xu + ((size_t)t * BATCH + b0 + er) * G4 + n0 + ec;
        float4 xva = __ldcg((const float4*)xp);
        float4 xvb = __ldcg((const float4*)(xp + 4));

        ull acc[2][4] = {};   // [rowpair(lanes=2 rows)][col]

        if (t > 0) {
            const float* aptr = h_in + (size_t)(b0 + prow) * HSZ + half * 256 + pkof;
            float4 pa = __ldcg((const float4*)aptr);
            float4 pb = __ldcg((const float4*)(aptr + 4));

            // store chunk 0 into buffer 0 (XOR-swizzled, conflict-free)
            {
                float* B0 = myA;
                B0[(pkof + 0) * AST + scol] = pa.x;
                B0[(pkof + 1) * AST + scol] = pa.y;
                B0[(pkof + 2) * AST + scol] = pa.z;
                B0[(pkof + 3) * AST + scol] = pa.w;
                B0[(pkof + 4) * AST + scol] = pb.x;
                B0[(pkof + 5) * AST + scol] = pb.y;
                B0[(pkof + 6) * AST + scol] = pb.z;
                B0[(pkof + 7) * AST + scol] = pb.w;
            }
            __syncthreads();

            for (int s = 0; s < 8; s++) {
                if (s < 7) {
                    pa = __ldcg((const float4*)(aptr + (s + 1) * CHUNK));
                    pb = __ldcg((const float4*)(aptr + (s + 1) * CHUNK + 4));
                }

                const float* Acur = myA + (s & 1) * ABUF_FLOATS;
                const float* WB = Whs + (size_t)(half * 256 + s * CHUNK) * PN + tx * 4;
#pragma unroll
                for (int kk = 0; kk < CHUNK; kk++) {
                    ulonglong2 a2 = *(const ulonglong2*)
                        &Acur[kk * AST + (ty4 ^ (((kk >> 3) & 3) * 8))];
                    float4 b4 = *(const float4*)(WB + kk * PN);
                    ull bd0 = dup2(b4.x), bd1 = dup2(b4.y);
                    ull bd2 = dup2(b4.z), bd3 = dup2(b4.w);
                    acc[0][0] = fma2(a2.x, bd0, acc[0][0]);
                    acc[1][0] = fma2(a2.y, bd0, acc[1][0]);
                    acc[0][1] = fma2(a2.x, bd1, acc[0][1]);
                    acc[1][1] = fma2(a2.y, bd1, acc[1][1]);
                    acc[0][2] = fma2(a2.x, bd2, acc[0][2]);
                    acc[1][2] = fma2(a2.y, bd2, acc[1][2]);
                    acc[0][3] = fma2(a2.x, bd3, acc[0][3]);
                    acc[1][3] = fma2(a2.y, bd3, acc[1][3]);
                }

                if (s < 7) {
                    float* Bnx = myA + ((s + 1) & 1) * ABUF_FLOATS;
                    Bnx[(pkof + 0) * AST + scol] = pa.x;
                    Bnx[(pkof + 1) * AST + scol] = pa.y;
                    Bnx[(pkof + 2) * AST + scol] = pa.z;
                    Bnx[(pkof + 3) * AST + scol] = pa.w;
                    Bnx[(pkof + 4) * AST + scol] = pb.x;
                    Bnx[(pkof + 5) * AST + scol] = pb.y;
                    Bnx[(pkof + 6) * AST + scol] = pb.z;
                    Bnx[(pkof + 7) * AST + scol] = pb.w;
                }
                __syncthreads();
            }
        }

        // ---- write partial accs to this half's EP buffer ----
        float* EPh = half ? EP1 : EP0;
#pragma unroll
        for (int rp = 0; rp < 2; rp++) {
            float2 c0 = unpk(acc[rp][0]);
            float2 c1 = unpk(acc[rp][1]);
            float2 c2 = unpk(acc[rp][2]);
            float2 c3 = unpk(acc[rp][3]);
            float4 lo = {c0.x, c1.x, c2.x, c3.x};   // row ty4 + 2rp
            float4 hi = {c0.y, c1.y, c2.y, c3.y};   // row ty4 + 2rp + 1
            *(float4*)&EPh[(ty4 + 2 * rp) * EPS + tx * 4] = lo;
            *(float4*)&EPh[(ty4 + 2 * rp + 1) * EPS + tx * 4] = hi;
        }
        __syncthreads();

        // ---- combine halves + fused LSTM cell (1 row, 2 units per thread) ----
        float4 pA = *(const float4*)&EP0[er * EPS + ec];
        float4 pB = *(const float4*)&EP0[er * EPS + ec + 4];
        float4 qA = *(const float4*)&EP1[er * EPS + ec];
        float4 qB = *(const float4*)&EP1[er * EPS + ec + 4];

        float iA = fsig (pA.x + qA.x + xva.x);
        float fA = fsig (pA.y + qA.y + xva.y);
        float gA = ftanh(pA.z + qA.z + xva.z);
        float oA = fsig (pA.w + qA.w + xva.w);
        float iB = fsig (pB.x + qB.x + xvb.x);
        float fB = fsig (pB.y + qB.y + xvb.y);
        float gB = ftanh(pB.z + qB.z + xvb.z);
        float oB = fsig (pB.w + qB.w + xvb.w);

        cA = fA * cA + iA * gA;
        cB = fB * cB + iB * gB;
        float2 hv = {oA * ftanh(cA), oB * ftanh(cB)};
        *(float2*)&h_out[(size_t)(b0 + er) * HSZ + uA] = hv;

        // ---- grid-wide sync (wrap-safe compare; tight acquire spin) ----
        if (t < SEQ - 1) {
            __syncthreads();
            if (tid == 0) {
                arrive_release(&g_arrive);
                unsigned target = (unsigned)(t + 1) * (unsigned)PBLKS;
                while ((int)(poll_acquire(&g_arrive) - target) < 0) { }
            }
            __syncthreads();
        }
    }
}

// ---------------- launch ----------------------------------------------------
extern "C" void kernel_launch(void* const* d_in, const int* in_sizes, int n_in,
                              void* d_out, int out_size) {
    const float* x   = (const float*)d_in[0];
    const float* Wui = (const float*)d_in[1];
    const float* Whi = (const float*)d_in[2];
    const float* bi  = (const float*)d_in[3];
    const float* Wuf = (const float*)d_in[4];
    const float* Whf = (const float*)d_in[5];
    const float* bf  = (const float*)d_in[6];
    const float* Wug = (const float*)d_in[7];
    const float* Whg = (const float*)d_in[8];
    const float* bg  = (const float*)d_in[9];
    const float* Wuo = (const float*)d_in[10];
    const float* Who = (const float*)d_in[11];
    const float* bo  = (const float*)d_in[12];
    float* out = (float*)d_out;

    cudaFuncSetAttribute(lstm_persistent,
                         cudaFuncAttributeMaxDynamicSharedMemorySize, P_SMEM_BYTES);

    dim3 xu_grid(G4 / XBN, (SEQ * BATCH) / XBM);   // (32, 2048)
    xu_kernel<<<xu_grid, 256>>>(x, Wui, Wuf, Wug, Wuo, bi, bf, bg, bo);

    lstm_persistent<<<PBLKS, 512, P_SMEM_BYTES>>>(out, Whi, Whf, Whg, Who);
}